// round 1
// baseline (speedup 1.0000x reference)
#include <cuda_runtime.h>

// RWKV v4 single-token forward, persistent-kernel formulation.
// One kernel launch, grid = #SMs (all blocks co-resident), software grid
// barriers between dependent GEMV stages. All small elementwise work (LN,
// time-mix, WKV recurrence) is recomputed redundantly per block in smem to
// minimize barrier count (4 per layer).

#define E   1024
#define HH  4096
#define NL  24
#define NV  50277
#define T   512
#define WPB (T / 32)

// ---- persistent device scratch (allocation-free rule: __device__ globals) ----
__device__ float g_x[E];        // residual stream
__device__ float g_kvr[3 * E];  // k, v, r pre-activations
__device__ float g_kk[HH];      // relu^2(fkw @ fxk)
__device__ float g_fr[E];       // sigmoid(frw @ fxr)
__device__ unsigned int g_bar[2];  // {count, generation} -- reset by memset each launch

struct P {
    const float *ctx, *state, *ln0w, *ln0b, *ln1w, *ln1b, *ln2w, *ln2b;
    const float *td, *tf, *tmk, *tmv, *tmr, *kw, *vw, *rw, *ow;
    const float *ftmk, *ftmr, *fkw, *frw, *fvw, *lnoutw, *lnoutb, *head;
    float* out;
    int nb;   // number of blocks (== #SMs)
    int ws;   // write new_state to out[NV..] ?
};

__device__ __forceinline__ void grid_sync(int nb) {
    __syncthreads();
    if (threadIdx.x == 0) {
        unsigned int gen = ((volatile unsigned int*)g_bar)[1];
        __threadfence();
        if (atomicAdd(&g_bar[0], 1u) == (unsigned int)(nb - 1)) {
            atomicExch(&g_bar[0], 0u);
            __threadfence();
            atomicAdd(&g_bar[1], 1u);
        } else {
            while (((volatile unsigned int*)g_bar)[1] == gen) { __nanosleep(64); }
        }
        __threadfence();
    }
    __syncthreads();
}

// block-wide sum of (a, b); result broadcast to all threads
__device__ __forceinline__ void block_reduce2(float& a, float& b, float* sr) {
    #pragma unroll
    for (int o = 16; o; o >>= 1) {
        a += __shfl_down_sync(0xFFFFFFFFu, a, o);
        b += __shfl_down_sync(0xFFFFFFFFu, b, o);
    }
    int w = threadIdx.x >> 5, l = threadIdx.x & 31;
    __syncthreads();
    if (l == 0) { sr[w] = a; sr[w + WPB] = b; }
    __syncthreads();
    if (threadIdx.x == 0) {
        float sa = 0.f, sb2 = 0.f;
        #pragma unroll
        for (int i = 0; i < WPB; i++) { sa += sr[i]; sb2 += sr[i + WPB]; }
        sr[2 * WPB] = sa; sr[2 * WPB + 1] = sb2;
    }
    __syncthreads();
    a = sr[2 * WPB];
    b = sr[2 * WPB + 1];
}

// warp computes dot(w[0..32*4*N4), x[...]) ; row length = 128*N4 floats
template <int N4>
__device__ __forceinline__ float warp_dot(const float* __restrict__ w,
                                          const float* x, int lane) {
    const float4* __restrict__ w4 = (const float4*)w;
    const float4* x4 = (const float4*)x;
    float acc0 = 0.f, acc1 = 0.f;
    #pragma unroll
    for (int u = 0; u < N4; u += 2) {
        float4 a = __ldg(&w4[lane + 32 * u]);
        float4 bx = x4[lane + 32 * u];
        acc0 += a.x * bx.x + a.y * bx.y + a.z * bx.z + a.w * bx.w;
        float4 a2 = __ldg(&w4[lane + 32 * (u + 1)]);
        float4 bx2 = x4[lane + 32 * (u + 1)];
        acc1 += a2.x * bx2.x + a2.y * bx2.y + a2.z * bx2.z + a2.w * bx2.w;
    }
    float acc = acc0 + acc1;
    #pragma unroll
    for (int o = 16; o; o >>= 1) acc += __shfl_down_sync(0xFFFFFFFFu, acc, o);
    return acc;
}

__global__ void __launch_bounds__(T, 1) rwkv_kernel(P p) {
    __shared__ float sb[4096];
    __shared__ float sr[2 * WPB + 2];
    const int tid = threadIdx.x, lane = tid & 31, warp = tid >> 5;
    const int gw = blockIdx.x * WPB + warp;
    const int NW = p.nb * WPB;
    float* outS = p.out + NV;

    // ---- x0 = LN(ctx, ln0) ----
    float s = 0.f, s2 = 0.f;
    for (int i = tid; i < E; i += T) { float v = p.ctx[i]; sb[i] = v; s += v; s2 += v * v; }
    block_reduce2(s, s2, sr);
    {
        float mu = s * (1.f / E);
        float rs = rsqrtf(s2 * (1.f / E) - mu * mu + 1e-5f);
        if (blockIdx.x == 0)
            for (int i = tid; i < E; i += T)
                g_x[i] = (sb[i] - mu) * rs * p.ln0w[i] + p.ln0b[i];
    }
    grid_sync(p.nb);

    for (int l = 0; l < NL; l++) {
        const float* st = p.state + (size_t)l * 5 * E;

        // ======== Stage A: LN1 + time-mix (redundant) + k/v/r GEMVs ========
        s = 0.f; s2 = 0.f;
        for (int i = tid; i < E; i += T) { float v = g_x[i]; sb[3072 + i] = v; s += v; s2 += v * v; }
        block_reduce2(s, s2, sr);
        {
            float mu = s * (1.f / E);
            float rs = rsqrtf(s2 * (1.f / E) - mu * mu + 1e-5f);
            const float* l1w = p.ln1w + l * E; const float* l1b = p.ln1b + l * E;
            const float* tmk = p.tmk + l * E; const float* tmv = p.tmv + l * E;
            const float* tmr = p.tmr + l * E; const float* sp = st + E;
            for (int i = tid; i < E; i += T) {
                float xn = (sb[3072 + i] - mu) * rs * l1w[i] + l1b[i];
                float spv = sp[i];
                float a = tmk[i], b = tmv[i], c = tmr[i];
                sb[i]        = xn * a + spv * (1.f - a);
                sb[1024 + i] = xn * b + spv * (1.f - b);
                sb[2048 + i] = xn * c + spv * (1.f - c);
                if (p.ws && blockIdx.x == 0) outS[(size_t)(5 * l + 1) * E + i] = xn;
            }
        }
        __syncthreads();
        {
            const float* W0 = p.kw + (size_t)l * E * E;
            const float* W1 = p.vw + (size_t)l * E * E;
            const float* W2 = p.rw + (size_t)l * E * E;
            for (int t = gw; t < 3 * E; t += NW) {
                int m = t >> 10, i = t & 1023;
                const float* w = (m == 0 ? W0 : (m == 1 ? W1 : W2)) + (size_t)i * E;
                float acc = warp_dot<8>(w, sb + (m << 10), lane);
                if (lane == 0) g_kvr[t] = acc;
            }
        }
        grid_sync(p.nb);

        // ======== Stage B: WKV recurrence (redundant) + ow GEMV ========
        {
            const float* aa = st + 2 * E; const float* bb = st + 3 * E; const float* pp = st + 4 * E;
            const float* tf = p.tf + l * E; const float* td = p.td + l * E;
            for (int i = tid; i < E; i += T) {
                float k = g_kvr[i], v = g_kvr[E + i], rr = g_kvr[2 * E + i];
                float A = aa[i], B = bb[i], Pp = pp[i];
                float ww = tf[i] + k;
                float q = fmaxf(Pp, ww);
                float e1 = __expf(Pp - q), e2 = __expf(ww - q);
                float num = e1 * A + e2 * v, den = e1 * B + e2;
                float r = 1.f / (1.f + __expf(-rr));
                sb[i] = r * num / den;
                float ww2 = Pp + td[i];
                float p2 = fmaxf(ww2, k);
                float e1b = __expf(ww2 - p2), e2b = __expf(k - p2);
                if (p.ws && blockIdx.x == 0) {
                    outS[(size_t)(5 * l + 2) * E + i] = e1b * A + e2b * v;
                    outS[(size_t)(5 * l + 3) * E + i] = e1b * B + e2b;
                    outS[(size_t)(5 * l + 4) * E + i] = p2;
                }
            }
        }
        __syncthreads();
        {
            const float* OW = p.ow + (size_t)l * E * E;
            for (int t = gw; t < E; t += NW) {
                float acc = warp_dot<8>(OW + (size_t)t * E, sb, lane);
                if (lane == 0) g_x[t] += acc;
            }
        }
        grid_sync(p.nb);

        // ======== Stage C: LN2 + chan-mix (redundant) + fk/fr GEMVs ========
        s = 0.f; s2 = 0.f;
        for (int i = tid; i < E; i += T) { float v = g_x[i]; sb[2048 + i] = v; s += v; s2 += v * v; }
        block_reduce2(s, s2, sr);
        {
            float mu = s * (1.f / E);
            float rs = rsqrtf(s2 * (1.f / E) - mu * mu + 1e-5f);
            const float* l2w = p.ln2w + l * E; const float* l2b = p.ln2b + l * E;
            const float* ftmk = p.ftmk + l * E; const float* ftmr = p.ftmr + l * E;
            const float* s0 = st;
            for (int i = tid; i < E; i += T) {
                float xn2 = (sb[2048 + i] - mu) * rs * l2w[i] + l2b[i];
                float sv = s0[i];
                float a = ftmk[i], b = ftmr[i];
                sb[i]        = xn2 * a + sv * (1.f - a);
                sb[1024 + i] = xn2 * b + sv * (1.f - b);
                if (p.ws && blockIdx.x == 0) outS[(size_t)(5 * l + 0) * E + i] = xn2;
            }
        }
        __syncthreads();
        {
            const float* FK = p.fkw + (size_t)l * HH * E;
            const float* FR = p.frw + (size_t)l * E * E;
            for (int t = gw; t < HH + E; t += NW) {
                if (t < HH) {
                    float acc = warp_dot<8>(FK + (size_t)t * E, sb, lane);
                    if (lane == 0) { float rl = fmaxf(acc, 0.f); g_kk[t] = rl * rl; }
                } else {
                    int i = t - HH;
                    float acc = warp_dot<8>(FR + (size_t)i * E, sb + 1024, lane);
                    if (lane == 0) g_fr[i] = 1.f / (1.f + __expf(-acc));
                }
            }
        }
        grid_sync(p.nb);

        // ======== Stage D: x += fr * (fvw @ kk) ========
        for (int i = tid; i < HH; i += T) sb[i] = g_kk[i];
        __syncthreads();
        {
            const float* FV = p.fvw + (size_t)l * E * HH;
            for (int t = gw; t < E; t += NW) {
                float acc = warp_dot<32>(FV + (size_t)t * HH, sb, lane);
                if (lane == 0) g_x[t] += g_fr[t] * acc;
            }
        }
        grid_sync(p.nb);
    }

    // ======== lnout + head GEMV ========
    s = 0.f; s2 = 0.f;
    for (int i = tid; i < E; i += T) { float v = g_x[i]; sb[1024 + i] = v; s += v; s2 += v * v; }
    block_reduce2(s, s2, sr);
    {
        float mu = s * (1.f / E);
        float rs = rsqrtf(s2 * (1.f / E) - mu * mu + 1e-5f);
        for (int i = tid; i < E; i += T)
            sb[i] = (sb[1024 + i] - mu) * rs * p.lnoutw[i] + p.lnoutb[i];
    }
    __syncthreads();
    for (int t = gw; t < NV; t += NW) {
        float acc = warp_dot<8>(p.head + (size_t)t * E, sb, lane);
        if (lane == 0) p.out[t] = acc;
    }
}

extern "C" void kernel_launch(void* const* d_in, const int* in_sizes, int n_in,
                              void* d_out, int out_size) {
    (void)in_sizes; (void)n_in;
    P p;
    p.ctx    = (const float*)d_in[0];
    p.state  = (const float*)d_in[1];
    p.ln0w   = (const float*)d_in[2];
    p.ln0b   = (const float*)d_in[3];
    p.ln1w   = (const float*)d_in[4];
    p.ln1b   = (const float*)d_in[5];
    p.ln2w   = (const float*)d_in[6];
    p.ln2b   = (const float*)d_in[7];
    p.td     = (const float*)d_in[8];
    p.tf     = (const float*)d_in[9];
    p.tmk    = (const float*)d_in[10];
    p.tmv    = (const float*)d_in[11];
    p.tmr    = (const float*)d_in[12];
    p.kw     = (const float*)d_in[13];
    p.vw     = (const float*)d_in[14];
    p.rw     = (const float*)d_in[15];
    p.ow     = (const float*)d_in[16];
    p.ftmk   = (const float*)d_in[17];
    p.ftmr   = (const float*)d_in[18];
    p.fkw    = (const float*)d_in[19];
    p.frw    = (const float*)d_in[20];
    p.fvw    = (const float*)d_in[21];
    p.lnoutw = (const float*)d_in[22];
    p.lnoutb = (const float*)d_in[23];
    p.head   = (const float*)d_in[24];
    p.out    = (float*)d_out;

    int dev = 0;
    cudaGetDevice(&dev);
    int nsm = 0;
    cudaDeviceGetAttribute(&nsm, cudaDevAttrMultiProcessorCount, dev);
    if (nsm <= 0) nsm = 148;
    p.nb = nsm;
    p.ws = (out_size >= NV + 5 * NL * E) ? 1 : 0;

    void* baddr = nullptr;
    cudaGetSymbolAddress(&baddr, g_bar);
    cudaMemsetAsync(baddr, 0, sizeof(unsigned int) * 2, 0);

    rwkv_kernel<<<nsm, T>>>(p);
}

// round 2
// speedup vs baseline: 1.0988x; 1.0988x over previous
#include <cuda_runtime.h>

// RWKV v4 single-token forward, persistent kernel, round 2.
// Changes vs R1: 1024 threads/block (2x warps in flight), all GEMV stages
// split into fine-grained half-row / quarter-row tasks with partial-sum
// combine done redundantly per block (deterministic, no atomics), residual
// stream kept in per-block shared memory (no global x round trips).

#define E   1024
#define HH  4096
#define NL  24
#define NV  50277
#define T   1024
#define WPB 32

// ---- persistent device scratch (__device__ globals; no allocation) ----
__device__ float g_kvrp[2][3 * E];  // k/v/r half-row partials
__device__ float g_op[2][E];        // ow half-row partials
__device__ float g_fkp[2][HH];      // ffn_k half-row partials (pre-relu)
__device__ float g_frp[2][E];       // ffn_r half-row partials (pre-sigmoid)
__device__ float g_fvp[4][E];       // ffn_v quarter-row partials
__device__ unsigned int g_bar[2];   // {count, generation}; memset per launch

struct P {
    const float *ctx, *state, *ln0w, *ln0b, *ln1w, *ln1b, *ln2w, *ln2b;
    const float *td, *tf, *tmk, *tmv, *tmr, *kw, *vw, *rw, *ow;
    const float *ftmk, *ftmr, *fkw, *frw, *fvw, *lnoutw, *lnoutb, *head;
    float* out;
    int nb;
    int ws;
};

__device__ __forceinline__ void grid_sync(int nb) {
    __syncthreads();
    if (threadIdx.x == 0) {
        unsigned int gen = ((volatile unsigned int*)g_bar)[1];
        __threadfence();
        if (atomicAdd(&g_bar[0], 1u) == (unsigned int)(nb - 1)) {
            atomicExch(&g_bar[0], 0u);
            __threadfence();
            atomicAdd(&g_bar[1], 1u);
        } else {
            while (((volatile unsigned int*)g_bar)[1] == gen) { __nanosleep(64); }
        }
        __threadfence();
    }
    __syncthreads();
}

__device__ __forceinline__ void block_reduce2(float& a, float& b, float* sr) {
    #pragma unroll
    for (int o = 16; o; o >>= 1) {
        a += __shfl_down_sync(0xFFFFFFFFu, a, o);
        b += __shfl_down_sync(0xFFFFFFFFu, b, o);
    }
    int w = threadIdx.x >> 5, l = threadIdx.x & 31;
    __syncthreads();
    if (l == 0) { sr[w] = a; sr[w + WPB] = b; }
    __syncthreads();
    if (threadIdx.x == 0) {
        float sa = 0.f, sb2 = 0.f;
        #pragma unroll
        for (int i = 0; i < WPB; i++) { sa += sr[i]; sb2 += sr[i + WPB]; }
        sr[2 * WPB] = sa; sr[2 * WPB + 1] = sb2;
    }
    __syncthreads();
    a = sr[2 * WPB];
    b = sr[2 * WPB + 1];
}

// warp dot over 128*N4 floats (N4 float4 per lane)
template <int N4>
__device__ __forceinline__ float warp_dot(const float* __restrict__ w,
                                          const float* x, int lane) {
    const float4* __restrict__ w4 = (const float4*)w;
    const float4* x4 = (const float4*)x;
    float acc0 = 0.f, acc1 = 0.f;
    #pragma unroll
    for (int u = 0; u < N4; u += 2) {
        float4 a = __ldg(&w4[lane + 32 * u]);
        float4 bx = x4[lane + 32 * u];
        acc0 += a.x * bx.x + a.y * bx.y + a.z * bx.z + a.w * bx.w;
        if (u + 1 < N4) {
            float4 a2 = __ldg(&w4[lane + 32 * (u + 1)]);
            float4 bx2 = x4[lane + 32 * (u + 1)];
            acc1 += a2.x * bx2.x + a2.y * bx2.y + a2.z * bx2.z + a2.w * bx2.w;
        }
    }
    float acc = acc0 + acc1;
    #pragma unroll
    for (int o = 16; o; o >>= 1) acc += __shfl_down_sync(0xFFFFFFFFu, acc, o);
    return acc;
}

__global__ void __launch_bounds__(T, 1) rwkv_kernel(P p) {
    __shared__ float sx[E];        // residual stream (identical in every block)
    __shared__ float sop[HH];      // operand buffer
    __shared__ float sred[2 * WPB + 2];
    const int tid = threadIdx.x, lane = tid & 31, warp = tid >> 5;
    const int gw = blockIdx.x * WPB + warp;
    const int NW = p.nb * WPB;
    const bool w0 = (p.ws && blockIdx.x == 0);
    float* outS = p.out + NV;

    // ---- x = LN(ctx, ln0), computed redundantly by every block ----
    float s = 0.f, s2 = 0.f;
    for (int i = tid; i < E; i += T) { float v = p.ctx[i]; sop[i] = v; s += v; s2 += v * v; }
    block_reduce2(s, s2, sred);
    {
        float mu = s * (1.f / E);
        float rs = rsqrtf(s2 * (1.f / E) - mu * mu + 1e-5f);
        for (int i = tid; i < E; i += T)
            sx[i] = (sop[i] - mu) * rs * p.ln0w[i] + p.ln0b[i];
    }
    __syncthreads();

    for (int l = 0; l < NL; l++) {
        const float* st = p.state + (size_t)l * 5 * E;

        // ======== Stage A: (combine prev FFN) + LN1 + time-mix + k/v/r GEMV ========
        if (l > 0) {
            for (int i = tid; i < E; i += T) {
                float fr = 1.f / (1.f + __expf(-(g_frp[0][i] + g_frp[1][i])));
                sx[i] += fr * (g_fvp[0][i] + g_fvp[1][i] + g_fvp[2][i] + g_fvp[3][i]);
            }
        }
        s = 0.f; s2 = 0.f;
        for (int i = tid; i < E; i += T) { float v = sx[i]; s += v; s2 += v * v; }
        block_reduce2(s, s2, sred);
        {
            float mu = s * (1.f / E);
            float rs = rsqrtf(s2 * (1.f / E) - mu * mu + 1e-5f);
            const float* l1w = p.ln1w + l * E; const float* l1b = p.ln1b + l * E;
            const float* tmk = p.tmk + l * E; const float* tmv = p.tmv + l * E;
            const float* tmr = p.tmr + l * E; const float* sp = st + E;
            for (int i = tid; i < E; i += T) {
                float xn = (sx[i] - mu) * rs * l1w[i] + l1b[i];
                float spv = sp[i];
                float a = tmk[i], b = tmv[i], c = tmr[i];
                sop[i]         = xn * a + spv * (1.f - a);
                sop[E + i]     = xn * b + spv * (1.f - b);
                sop[2 * E + i] = xn * c + spv * (1.f - c);
                if (w0) outS[(size_t)(5 * l + 1) * E + i] = xn;
            }
        }
        __syncthreads();
        {
            const float* Wk = p.kw + (size_t)l * E * E;
            const float* Wv = p.vw + (size_t)l * E * E;
            const float* Wr = p.rw + (size_t)l * E * E;
            for (int t = gw; t < 6144; t += NW) {
                int h = t & 1, r = t >> 1, m = r >> 10, i = r & 1023;
                const float* w = (m == 0 ? Wk : (m == 1 ? Wv : Wr)) + (size_t)i * E + h * 512;
                float acc = warp_dot<4>(w, sop + m * E + h * 512, lane);
                if (lane == 0) g_kvrp[h][m * E + i] = acc;
            }
        }
        grid_sync(p.nb);

        // ======== Stage B: WKV (redundant) + ow GEMV ========
        {
            const float* aa = st + 2 * E; const float* bb = st + 3 * E; const float* pp = st + 4 * E;
            const float* tf = p.tf + l * E; const float* td = p.td + l * E;
            for (int i = tid; i < E; i += T) {
                float k  = g_kvrp[0][i] + g_kvrp[1][i];
                float v  = g_kvrp[0][E + i] + g_kvrp[1][E + i];
                float rr = g_kvrp[0][2 * E + i] + g_kvrp[1][2 * E + i];
                float A = aa[i], B = bb[i], Pp = pp[i];
                float ww = tf[i] + k;
                float q = fmaxf(Pp, ww);
                float e1 = __expf(Pp - q), e2 = __expf(ww - q);
                float num = e1 * A + e2 * v, den = e1 * B + e2;
                float r = 1.f / (1.f + __expf(-rr));
                sop[i] = r * num / den;
                if (w0) {
                    float ww2 = Pp + td[i];
                    float p2 = fmaxf(ww2, k);
                    float e1b = __expf(ww2 - p2), e2b = __expf(k - p2);
                    outS[(size_t)(5 * l + 2) * E + i] = e1b * A + e2b * v;
                    outS[(size_t)(5 * l + 3) * E + i] = e1b * B + e2b;
                    outS[(size_t)(5 * l + 4) * E + i] = p2;
                }
            }
        }
        __syncthreads();
        {
            const float* OW = p.ow + (size_t)l * E * E;
            for (int t = gw; t < 2048; t += NW) {
                int h = t & 1, i = t >> 1;
                float acc = warp_dot<4>(OW + (size_t)i * E + h * 512, sop + h * 512, lane);
                if (lane == 0) g_op[h][i] = acc;
            }
        }
        grid_sync(p.nb);

        // ======== Stage C: x += ow; LN2 + chan-mix + fk/fr GEMV ========
        for (int i = tid; i < E; i += T) sx[i] += g_op[0][i] + g_op[1][i];
        s = 0.f; s2 = 0.f;
        for (int i = tid; i < E; i += T) { float v = sx[i]; s += v; s2 += v * v; }
        block_reduce2(s, s2, sred);
        {
            float mu = s * (1.f / E);
            float rs = rsqrtf(s2 * (1.f / E) - mu * mu + 1e-5f);
            const float* l2w = p.ln2w + l * E; const float* l2b = p.ln2b + l * E;
            const float* ftmk = p.ftmk + l * E; const float* ftmr = p.ftmr + l * E;
            const float* s0 = st;
            for (int i = tid; i < E; i += T) {
                float xn2 = (sx[i] - mu) * rs * l2w[i] + l2b[i];
                float sv = s0[i];
                float a = ftmk[i], b = ftmr[i];
                sop[i]     = xn2 * a + sv * (1.f - a);
                sop[E + i] = xn2 * b + sv * (1.f - b);
                if (w0) outS[(size_t)(5 * l + 0) * E + i] = xn2;
            }
        }
        __syncthreads();
        {
            const float* FK = p.fkw + (size_t)l * HH * E;
            const float* FR = p.frw + (size_t)l * E * E;
            for (int t = gw; t < 10240; t += NW) {
                if (t < 8192) {
                    int h = t & 1, i = t >> 1;
                    float acc = warp_dot<4>(FK + (size_t)i * E + h * 512, sop + h * 512, lane);
                    if (lane == 0) g_fkp[h][i] = acc;
                } else {
                    int t2 = t - 8192;
                    int h = t2 & 1, i = t2 >> 1;
                    float acc = warp_dot<4>(FR + (size_t)i * E + h * 512, sop + E + h * 512, lane);
                    if (lane == 0) g_frp[h][i] = acc;
                }
            }
        }
        grid_sync(p.nb);

        // ======== Stage D: kk = relu^2(fk); fv GEMV (quarter rows) ========
        for (int i = tid; i < HH; i += T) {
            float a = fmaxf(g_fkp[0][i] + g_fkp[1][i], 0.f);
            sop[i] = a * a;
        }
        __syncthreads();
        {
            const float* FV = p.fvw + (size_t)l * E * HH;
            for (int t = gw; t < 4096; t += NW) {
                int c = t & 3, i = t >> 2;
                float acc = warp_dot<8>(FV + (size_t)i * HH + c * E, sop + c * E, lane);
                if (lane == 0) g_fvp[c][i] = acc;
            }
        }
        grid_sync(p.nb);
    }

    // ======== final: combine last FFN, LN_out, head GEMV ========
    for (int i = tid; i < E; i += T) {
        float fr = 1.f / (1.f + __expf(-(g_frp[0][i] + g_frp[1][i])));
        sx[i] += fr * (g_fvp[0][i] + g_fvp[1][i] + g_fvp[2][i] + g_fvp[3][i]);
    }
    s = 0.f; s2 = 0.f;
    for (int i = tid; i < E; i += T) { float v = sx[i]; s += v; s2 += v * v; }
    block_reduce2(s, s2, sred);
    {
        float mu = s * (1.f / E);
        float rs = rsqrtf(s2 * (1.f / E) - mu * mu + 1e-5f);
        for (int i = tid; i < E; i += T)
            sop[i] = (sx[i] - mu) * rs * p.lnoutw[i] + p.lnoutb[i];
    }
    __syncthreads();
    for (int t = gw; t < NV; t += NW) {
        float acc = warp_dot<8>(p.head + (size_t)t * E, sop, lane);
        if (lane == 0) p.out[t] = acc;
    }
}

extern "C" void kernel_launch(void* const* d_in, const int* in_sizes, int n_in,
                              void* d_out, int out_size) {
    (void)in_sizes; (void)n_in;
    P p;
    p.ctx    = (const float*)d_in[0];
    p.state  = (const float*)d_in[1];
    p.ln0w   = (const float*)d_in[2];
    p.ln0b   = (const float*)d_in[3];
    p.ln1w   = (const float*)d_in[4];
    p.ln1b   = (const float*)d_in[5];
    p.ln2w   = (const float*)d_in[6];
    p.ln2b   = (const float*)d_in[7];
    p.td     = (const float*)d_in[8];
    p.tf     = (const float*)d_in[9];
    p.tmk    = (const float*)d_in[10];
    p.tmv    = (const float*)d_in[11];
    p.tmr    = (const float*)d_in[12];
    p.kw     = (const float*)d_in[13];
    p.vw     = (const float*)d_in[14];
    p.rw     = (const float*)d_in[15];
    p.ow     = (const float*)d_in[16];
    p.ftmk   = (const float*)d_in[17];
    p.ftmr   = (const float*)d_in[18];
    p.fkw    = (const float*)d_in[19];
    p.frw    = (const float*)d_in[20];
    p.fvw    = (const float*)d_in[21];
    p.lnoutw = (const float*)d_in[22];
    p.lnoutb = (const float*)d_in[23];
    p.head   = (const float*)d_in[24];
    p.out    = (float*)d_out;

    int dev = 0;
    cudaGetDevice(&dev);
    int nsm = 0;
    cudaDeviceGetAttribute(&nsm, cudaDevAttrMultiProcessorCount, dev);
    if (nsm <= 0) nsm = 148;
    p.nb = nsm;
    p.ws = (out_size >= NV + 5 * NL * E) ? 1 : 0;

    void* baddr = nullptr;
    cudaGetSymbolAddress(&baddr, g_bar);
    cudaMemsetAsync(baddr, 0, sizeof(unsigned int) * 2, 0);

    rwkv_kernel<<<nsm, T>>>(p);
}